// round 14
// baseline (speedup 1.0000x reference)
#include <cuda_runtime.h>
#include <cstddef>

// Problem constants (B=16, N=M=1024, D=32)
#define CELEM (16 * 1024 * 1024)
#define ROWS  (16 * 1024)
#define NBLK  128                  // persistent blocks (co-resident, proven)

// eps = 1e-3
#define K2F       1442.6951f       // log2(e)/eps
#define EPSLN2F   6.9314718e-4f    // eps*ln2
#define EPSLOGMU  (-6.9314616e-3f) // eps*log(1/1024 + 1e-8)
#define QSCALE    32.0f            // s16 quantization scale
#define MARGIN_U  5                // prefilter margin in s16 units (0.156; need >2.9)

// Device scratch (allocation-free rule)
__device__ float g_C  [CELEM];     // fp32 C  (exact pass + final)
__device__ float g_CT [CELEM];     // fp32 C^T
__device__ short g_Cq [CELEM];     // s16  -round(32*C)   (DPX prefilter)
__device__ short g_CTq[CELEM];     // s16  -round(32*C^T)
__device__ float g_u[ROWS], g_v[ROWS];
__device__ float g_bp[NBLK];
__device__ int   g_done;
__device__ int   g_bar_count;
__device__ volatile int g_bar_gen;

// ---------------------------------------------------------------------------
__device__ __forceinline__ void gbarrier() {
    __syncthreads();
    if (threadIdx.x == 0) {
        __threadfence();
        int gen = g_bar_gen;
        if (atomicAdd(&g_bar_count, 1) == NBLK - 1) {
            g_bar_count = 0;
            __threadfence();
            g_bar_gen = gen + 1;
        } else {
            while (g_bar_gen == gen) __nanosleep(64);
        }
        __threadfence();
    }
    __syncthreads();
}

__device__ __forceinline__ float wred_max(float v) {
#pragma unroll
    for (int o = 16; o; o >>= 1) v = fmaxf(v, __shfl_xor_sync(0xffffffffu, v, o));
    return v;
}
__device__ __forceinline__ float wred_sum(float v) {
#pragma unroll
    for (int o = 16; o; o >>= 1) v += __shfl_xor_sync(0xffffffffu, v, o);
    return v;
}
// max of the two s16 halves of a packed word
__device__ __forceinline__ int smax2(unsigned p) {
    int lo = (int)(short)(p & 0xffffu);
    int hi = (int)(short)(p >> 16);
    return lo > hi ? lo : hi;
}
__device__ __forceinline__ unsigned packw(float a, float b) {
    int ia = __float2int_rn(a * QSCALE);
    int ib = __float2int_rn(b * QSCALE);
    return (unsigned)(ia & 0xffff) | ((unsigned)ib << 16);
}

// DPX prefilter of group Q (8 s16/lane = 256 elems): two subgroup running maxima.
// acc = max(wq + (-Cq), acc) per s16 lane, one VIADDMAX per 2 elements.
#define PREF_Q(Q) do {                                                          \
    uint4 cq = cp[((Q) << 5) + lane];                                           \
    accs[2*(Q)  ] = __viaddmax_s16x2(wq[(Q)*4+0], cq.x, accs[2*(Q)  ]);         \
    accs[2*(Q)  ] = __viaddmax_s16x2(wq[(Q)*4+1], cq.y, accs[2*(Q)  ]);         \
    accs[2*(Q)+1] = __viaddmax_s16x2(wq[(Q)*4+2], cq.z, accs[2*(Q)+1]);         \
    accs[2*(Q)+1] = __viaddmax_s16x2(wq[(Q)*4+3], cq.w, accs[2*(Q)+1]);         \
} while (0)

#define BUILD_WQ() do {                                                         \
    _Pragma("unroll")                                                           \
    for (int q = 0; q < 4; q++) {                                               \
        float4 wa = ws4[(q << 6) + (lane << 1)];                                \
        float4 wb = ws4[(q << 6) + (lane << 1) + 1];                            \
        wq[q*4+0] = packw(wa.x, wa.y);                                          \
        wq[q*4+1] = packw(wa.z, wa.w);                                          \
        wq[q*4+2] = packw(wb.x, wb.y);                                          \
        wq[q*4+3] = packw(wb.z, wb.w);                                          \
    }                                                                           \
} while (0)

// ---------------------------------------------------------------------------
// Cost matrix (verified): fp32 C/C^T + quantized -32*C as s16.
// ---------------------------------------------------------------------------
__global__ void __launch_bounds__(256) k_cost(const float* __restrict__ X,
                                              const float* __restrict__ Y) {
    __shared__ float xs[32][33], ys[32][33], cs[32][33];
    int t  = blockIdx.x;
    int b  = t >> 10;
    int it = (t >> 5) & 31;
    int jt = t & 31;
    int tid = threadIdx.x;
    int r = tid >> 5, d = tid & 31;

#pragma unroll
    for (int k = 0; k < 4; k++) {
        int rr = r + (k << 3);
        xs[rr][d] = X[((size_t)b * 1024 + it * 32 + rr) * 32 + d];
        ys[rr][d] = Y[((size_t)b * 1024 + jt * 32 + rr) * 32 + d];
    }
    __syncthreads();

    int tx = tid & 31, ty = tid >> 5;
#pragma unroll
    for (int k = 0; k < 4; k++) {
        int i = ty * 4 + k;
        float acc = 0.f;
#pragma unroll
        for (int dd = 0; dd < 32; dd++) {
            float diff = xs[i][dd] - ys[tx][dd];
            acc = fmaf(diff, diff, acc);
        }
        cs[i][tx] = acc;
    }
    __syncthreads();

    size_t cbase = (size_t)b << 20;
#pragma unroll
    for (int k = 0; k < 4; k++) {
        int i = ty * 4 + k;
        size_t idx  = cbase + (size_t)(it * 32 + i) * 1024 + jt * 32 + tx;
        size_t idxT = cbase + (size_t)(jt * 32 + i) * 1024 + it * 32 + tx;
        float  cv  = cs[i][tx];
        float  cvT = cs[tx][i];
        g_C  [idx]  = cv;
        g_CT [idxT] = cvT;
        g_Cq [idx]  = (short)__float2int_rn(cv  * -QSCALE);
        g_CTq[idxT] = (short)__float2int_rn(cvT * -QSCALE);
    }
}

// ---------------------------------------------------------------------------
// One half-step for this block's 128 rows (4 rows/warp).
// DPX s16 prefilter -> exact fp32 max + exp-sum over flagged subgroups.
// ---------------------------------------------------------------------------
template <bool MODE0>
__device__ __forceinline__ void scan_phase(
    int bid, int tid, int lane, int wid,
    const short* __restrict__ Cq, const float* __restrict__ Cf,
    const float* __restrict__ wsrc, float* __restrict__ zdst,
    float* ws, float* du_s)
{
    int b = bid >> 3;                       // batch of this block's 128 rows
    ws[tid] = wsrc[(b << 10) + tid];        // stage dual vector (fp32)
    __syncthreads();

    const float4* ws4 = (const float4*)ws;
    unsigned wq[16];
    BUILD_WQ();

#pragma unroll 1
    for (int r = 0; r < 4; r++) {
        int rl  = (wid << 2) + r;
        int row = (bid << 7) + rl;
        const uint4*  cp  = (const uint4*) (Cq + ((size_t)row << 10));
        const float4* cf4 = (const float4*)(Cf + ((size_t)row << 10));

        unsigned accs[8];
#pragma unroll
        for (int g = 0; g < 8; g++) accs[g] = 0x80008000u;   // -32768 each half
        PREF_Q(0); PREF_Q(1); PREF_Q(2); PREF_Q(3);

        // packed row max -> warp reduce -> scalar int max
        unsigned mm = __vmaxs2(__vmaxs2(__vmaxs2(accs[0], accs[1]),
                                        __vmaxs2(accs[2], accs[3])),
                               __vmaxs2(__vmaxs2(accs[4], accs[5]),
                                        __vmaxs2(accs[6], accs[7])));
#pragma unroll
        for (int o = 16; o; o >>= 1)
            mm = __vmaxs2(mm, __shfl_xor_sync(0xffffffffu, mm, o));
        int m_int = smax2(mm);

        int thr = m_int - MARGIN_U;
        int msk = 0;
#pragma unroll
        for (int g = 0; g < 8; g++) msk |= (smax2(accs[g]) > thr) << g;

        // exact fp32 max over flagged subgroups (argmax guaranteed flagged)
        float me = -3.4e38f;
#pragma unroll 1
        for (int q = 0; q < 4; q++) {
            int ix = (q << 6) + (lane << 1);
            if ((msk >> (2 * q)) & 1) {
                float4 a  = cf4[ix];
                float4 wa = ws4[ix];
                me = fmaxf(me, fmaxf(fmaxf(wa.x - a.x, wa.y - a.y),
                                     fmaxf(wa.z - a.z, wa.w - a.w)));
            }
            if ((msk >> (2 * q + 1)) & 1) {
                float4 bb = cf4[ix + 1];
                float4 wb = ws4[ix + 1];
                me = fmaxf(me, fmaxf(fmaxf(wb.x - bb.x, wb.y - bb.y),
                                     fmaxf(wb.z - bb.z, wb.w - bb.w)));
            }
        }
        me = wred_max(me);

        float s = 0.f;
#pragma unroll 1
        for (int q = 0; q < 4; q++) {
            int ix = (q << 6) + (lane << 1);
            if ((msk >> (2 * q)) & 1) {
                float4 a  = cf4[ix];                  // L1 hit
                float4 wa = ws4[ix];
                s += exp2f((wa.x - a.x - me) * K2F) + exp2f((wa.y - a.y - me) * K2F)
                   + exp2f((wa.z - a.z - me) * K2F) + exp2f((wa.w - a.w - me) * K2F);
            }
            if ((msk >> (2 * q + 1)) & 1) {
                float4 bb = cf4[ix + 1];
                float4 wb = ws4[ix + 1];
                s += exp2f((wb.x - bb.x - me) * K2F) + exp2f((wb.y - bb.y - me) * K2F)
                   + exp2f((wb.z - bb.z - me) * K2F) + exp2f((wb.w - bb.w - me) * K2F);
            }
        }
        s = wred_sum(s);

        if (lane == 0) {
            float z = EPSLOGMU - me - EPSLN2F * log2f(s);
            if (MODE0) du_s[rl] = fabsf(z - zdst[row]);
            zdst[row] = z;
        }
    }

    if (MODE0) {
        __syncthreads();
        if (wid == 0) {
            float e = du_s[lane] + du_s[lane + 32] + du_s[lane + 64] + du_s[lane + 96];
            e = wred_sum(e);
            if (lane == 0) g_bp[bid] = e;
        }
    }
}

// ---------------------------------------------------------------------------
// Persistent Sinkhorn kernel (champion control flow).
// ---------------------------------------------------------------------------
__global__ void __launch_bounds__(1024, 1) k_sink(float* __restrict__ out) {
    __shared__ float ws[1024];
    __shared__ float du_s[128];
    int tid  = threadIdx.x, bid = blockIdx.x;
    int lane = tid & 31,    wid = tid >> 5;

    // re-init per graph replay
    if (tid < 128) { int r = (bid << 7) + tid; g_u[r] = 0.f; g_v[r] = 0.f; }
    if (bid == 0 && tid == 0) g_done = 0;
    gbarrier();

    for (int it = 0; it < 100; it++) {
        int done = *(volatile int*)&g_done;     // frozen once latched (ref semantics)
        if (!done)
            scan_phase<true >(bid, tid, lane, wid, g_Cq,  g_C,  g_v, g_u, ws, du_s);
        gbarrier();
        if (!done) {
            if (bid == 0 && wid == 0) {         // err from this iteration's du
                float e = g_bp[lane] + g_bp[lane + 32] + g_bp[lane + 64] + g_bp[lane + 96];
                e = wred_sum(e);
                if (lane == 0 && e * (1.0f / 16.0f) < 0.1f) g_done = 1;
            }
            // triggering iteration's v-update still applied (matches reference)
            scan_phase<false>(bid, tid, lane, wid, g_CTq, g_CT, g_u, g_v, ws, du_s);
        }
        gbarrier();
    }

    // --------- final: sum_ij exp((u_i + v_j - C_ij)/eps) * C_ij ----------
    {
        int b = bid >> 3;
        ws[tid] = g_v[(b << 10) + tid];
        __syncthreads();
        const float4* ws4 = (const float4*)ws;
        unsigned wq[16];
        BUILD_WQ();

#pragma unroll 1
        for (int r = 0; r < 4; r++) {
            int rl  = (wid << 2) + r;
            int row = (bid << 7) + rl;
            const uint4*  cp  = (const uint4*) (g_Cq + ((size_t)row << 10));
            const float4* cf4 = (const float4*)(g_C  + ((size_t)row << 10));
            float uk = g_u[row];

            unsigned accs[8];
#pragma unroll
            for (int g = 0; g < 8; g++) accs[g] = 0x80008000u;
            PREF_Q(0); PREF_Q(1); PREF_Q(2); PREF_Q(3);

            // contribute iff (val + uk) > ~-0.03; generous slack for quantization
            int cutq = __float2int_rd((-0.6f - uk) * QSCALE);
            int msk = 0;
#pragma unroll
            for (int g = 0; g < 8; g++) msk |= (smax2(accs[g]) > cutq) << g;

            float s = 0.f;
#pragma unroll 1
            for (int q = 0; q < 4; q++) {
                int ix = (q << 6) + (lane << 1);
                if ((msk >> (2 * q)) & 1) {
                    float4 a  = cf4[ix];
                    float4 wa = ws4[ix];
                    s += exp2f((wa.x - a.x + uk) * K2F) * a.x
                       + exp2f((wa.y - a.y + uk) * K2F) * a.y
                       + exp2f((wa.z - a.z + uk) * K2F) * a.z
                       + exp2f((wa.w - a.w + uk) * K2F) * a.w;
                }
                if ((msk >> (2 * q + 1)) & 1) {
                    float4 bb = cf4[ix + 1];
                    float4 wb = ws4[ix + 1];
                    s += exp2f((wb.x - bb.x + uk) * K2F) * bb.x
                       + exp2f((wb.y - bb.y + uk) * K2F) * bb.y
                       + exp2f((wb.z - bb.z + uk) * K2F) * bb.z
                       + exp2f((wb.w - bb.w + uk) * K2F) * bb.w;
                }
            }
            s = wred_sum(s);
            if (lane == 0) du_s[rl] = s;
        }
        __syncthreads();
        if (wid == 0) {
            float e = du_s[lane] + du_s[lane + 32] + du_s[lane + 64] + du_s[lane + 96];
            e = wred_sum(e);
            if (lane == 0) g_bp[bid] = e;
        }
    }
    gbarrier();
    if (bid == 0 && wid == 0) {
        float e = g_bp[lane] + g_bp[lane + 32] + g_bp[lane + 64] + g_bp[lane + 96];
        e = wred_sum(e);
        if (lane == 0) out[0] = e * (1.0f / 16.0f);   // mean over B
    }
}

// ---------------------------------------------------------------------------
extern "C" void kernel_launch(void* const* d_in, const int* in_sizes, int n_in,
                              void* d_out, int out_size) {
    (void)in_sizes; (void)n_in; (void)out_size;
    const float* X = (const float*)d_in[0];   // output [16,1024,32]
    const float* Y = (const float*)d_in[1];   // labels [16,1024,32]

    k_cost<<<16384, 256>>>(X, Y);
    k_sink<<<NBLK, 1024>>>((float*)d_out);
}

// round 16
// speedup vs baseline: 1.2316x; 1.2316x over previous
#include <cuda_runtime.h>
#include <cstddef>

// Problem constants (B=16, N=M=1024, D=32)
#define CELEM (16 * 1024 * 1024)
#define ROWS  (16 * 1024)
#define NBLK  128                  // persistent blocks (co-resident, proven)

// eps = 1e-3
#define K2F       1442.6951f       // log2(e)/eps
#define EPSLN2F   6.9314718e-4f    // eps*ln2
#define EPSLOGMU  (-6.9314616e-3f) // eps*log(1/1024 + 1e-8)
#define QSCALE    32.0f            // s16 quantization scale
#define QINV      0.03125f         // 1/32
#define SHIFTC    45.084222f       // K2F / 32
#define MARGIN_U  5                // prefilter margin, s16 units (need > 2.89)

// Device scratch (allocation-free rule)
__device__ float g_C  [CELEM];     // fp32 C  (exp pass + final)
__device__ float g_CT [CELEM];     // fp32 C^T
__device__ short g_Cq [CELEM];     // s16  -round(32*C)   (DPX prefilter)
__device__ short g_CTq[CELEM];     // s16  -round(32*C^T)
__device__ float g_u[ROWS], g_v[ROWS];
__device__ float g_bp[NBLK];
__device__ int   g_done;
__device__ int   g_bar_count;
__device__ volatile int g_bar_gen;

// ---------------------------------------------------------------------------
__device__ __forceinline__ void gbarrier() {
    __syncthreads();
    if (threadIdx.x == 0) {
        __threadfence();
        int gen = g_bar_gen;
        if (atomicAdd(&g_bar_count, 1) == NBLK - 1) {
            g_bar_count = 0;
            __threadfence();
            g_bar_gen = gen + 1;
        } else {
            while (g_bar_gen == gen) __nanosleep(64);
        }
        __threadfence();
    }
    __syncthreads();
}

__device__ __forceinline__ float wred_sum(float v) {
#pragma unroll
    for (int o = 16; o; o >>= 1) v += __shfl_xor_sync(0xffffffffu, v, o);
    return v;
}
// max of the two s16 halves of a packed word
__device__ __forceinline__ int smax2(unsigned p) {
    int lo = (int)(short)(p & 0xffffu);
    int hi = (int)(short)(p >> 16);
    return lo > hi ? lo : hi;
}
__device__ __forceinline__ unsigned packw(float a, float b) {
    int ia = __float2int_rn(a * QSCALE);
    int ib = __float2int_rn(b * QSCALE);
    return (unsigned)(ia & 0xffff) | ((unsigned)ib << 16);
}

#define BUILD_WQ() do {                                                         \
    _Pragma("unroll")                                                           \
    for (int q = 0; q < 4; q++) {                                               \
        float4 wa = ws4[(q << 6) + (lane << 1)];                                \
        float4 wb = ws4[(q << 6) + (lane << 1) + 1];                            \
        wq[q*4+0] = packw(wa.x, wa.y);                                          \
        wq[q*4+1] = packw(wa.z, wa.w);                                          \
        wq[q*4+2] = packw(wb.x, wb.y);                                          \
        wq[q*4+3] = packw(wb.z, wb.w);                                          \
    }                                                                           \
} while (0)

// ---------------------------------------------------------------------------
// Cost matrix (verified): fp32 C/C^T + quantized -32*C as s16.
// ---------------------------------------------------------------------------
__global__ void __launch_bounds__(256) k_cost(const float* __restrict__ X,
                                              const float* __restrict__ Y) {
    __shared__ float xs[32][33], ys[32][33], cs[32][33];
    int t  = blockIdx.x;
    int b  = t >> 10;
    int it = (t >> 5) & 31;
    int jt = t & 31;
    int tid = threadIdx.x;
    int r = tid >> 5, d = tid & 31;

#pragma unroll
    for (int k = 0; k < 4; k++) {
        int rr = r + (k << 3);
        xs[rr][d] = X[((size_t)b * 1024 + it * 32 + rr) * 32 + d];
        ys[rr][d] = Y[((size_t)b * 1024 + jt * 32 + rr) * 32 + d];
    }
    __syncthreads();

    int tx = tid & 31, ty = tid >> 5;
#pragma unroll
    for (int k = 0; k < 4; k++) {
        int i = ty * 4 + k;
        float acc = 0.f;
#pragma unroll
        for (int dd = 0; dd < 32; dd++) {
            float diff = xs[i][dd] - ys[tx][dd];
            acc = fmaf(diff, diff, acc);
        }
        cs[i][tx] = acc;
    }
    __syncthreads();

    size_t cbase = (size_t)b << 20;
#pragma unroll
    for (int k = 0; k < 4; k++) {
        int i = ty * 4 + k;
        size_t idx  = cbase + (size_t)(it * 32 + i) * 1024 + jt * 32 + tx;
        size_t idxT = cbase + (size_t)(jt * 32 + i) * 1024 + it * 32 + tx;
        float  cv  = cs[i][tx];
        float  cvT = cs[tx][i];
        g_C  [idx]  = cv;
        g_CT [idxT] = cvT;
        g_Cq [idx]  = (short)__float2int_rn(cv  * -QSCALE);
        g_CTq[idxT] = (short)__float2int_rn(cvT * -QSCALE);
    }
}

// ---------------------------------------------------------------------------
// One half-step for this block's 128 rows, processed in PAIRS per warp.
// DPX s16 prefilter -> quantized-max shift -> single fp32 exp pass.
// (Exact-max pass removed: LSE is shift-invariant; quantized max is within
//  1/32 of true max => exponents bounded by ~45 bits, fp32-safe.)
// ---------------------------------------------------------------------------
template <bool MODE0>
__device__ __forceinline__ void scan_phase(
    int bid, int tid, int lane, int wid,
    const short* __restrict__ Cq, const float* __restrict__ Cf,
    const float* __restrict__ wsrc, float* __restrict__ zdst,
    float* ws, float* du_s)
{
    int b = bid >> 3;                       // batch of this block's 128 rows
    ws[tid] = wsrc[(b << 10) + tid];        // stage dual vector (fp32)
    __syncthreads();

    const float4* ws4 = (const float4*)ws;
    unsigned wq[16];
    BUILD_WQ();

#pragma unroll 1
    for (int p = 0; p < 2; p++) {
        int rlA  = (wid << 2) + (p << 1);
        int rowA = (bid << 7) + rlA;
        const uint4*  cpA = (const uint4*) (Cq + ((size_t)rowA << 10));
        const uint4*  cpB = (const uint4*) (Cq + ((size_t)(rowA + 1) << 10));
        const float4* cfA = (const float4*)(Cf + ((size_t)rowA << 10));
        const float4* cfB = (const float4*)(Cf + ((size_t)(rowA + 1) << 10));

        unsigned aA[8], aB[8];
#pragma unroll
        for (int g = 0; g < 8; g++) { aA[g] = 0x80008000u; aB[g] = 0x80008000u; }

        // interleaved loads + DPX chains (2x MLP, 2 independent dep chains)
#pragma unroll
        for (int q = 0; q < 4; q++) {
            uint4 cA = cpA[(q << 5) + lane];
            uint4 cB = cpB[(q << 5) + lane];
            aA[2*q  ] = __viaddmax_s16x2(wq[q*4+0], cA.x, aA[2*q  ]);
            aB[2*q  ] = __viaddmax_s16x2(wq[q*4+0], cB.x, aB[2*q  ]);
            aA[2*q  ] = __viaddmax_s16x2(wq[q*4+1], cA.y, aA[2*q  ]);
            aB[2*q  ] = __viaddmax_s16x2(wq[q*4+1], cB.y, aB[2*q  ]);
            aA[2*q+1] = __viaddmax_s16x2(wq[q*4+2], cA.z, aA[2*q+1]);
            aB[2*q+1] = __viaddmax_s16x2(wq[q*4+2], cB.z, aB[2*q+1]);
            aA[2*q+1] = __viaddmax_s16x2(wq[q*4+3], cA.w, aA[2*q+1]);
            aB[2*q+1] = __viaddmax_s16x2(wq[q*4+3], cB.w, aB[2*q+1]);
        }

        // packed row max + interleaved warp reductions
        unsigned mmA = __vmaxs2(__vmaxs2(__vmaxs2(aA[0], aA[1]), __vmaxs2(aA[2], aA[3])),
                                __vmaxs2(__vmaxs2(aA[4], aA[5]), __vmaxs2(aA[6], aA[7])));
        unsigned mmB = __vmaxs2(__vmaxs2(__vmaxs2(aB[0], aB[1]), __vmaxs2(aB[2], aB[3])),
                                __vmaxs2(__vmaxs2(aB[4], aB[5]), __vmaxs2(aB[6], aB[7])));
#pragma unroll
        for (int o = 16; o; o >>= 1) {
            mmA = __vmaxs2(mmA, __shfl_xor_sync(0xffffffffu, mmA, o));
            mmB = __vmaxs2(mmB, __shfl_xor_sync(0xffffffffu, mmB, o));
        }
        int miA = smax2(mmA), miB = smax2(mmB);

        int thrA = miA - MARGIN_U, thrB = miB - MARGIN_U;
        int mskA = 0, mskB = 0;
#pragma unroll
        for (int g = 0; g < 8; g++) {
            mskA |= (smax2(aA[g]) > thrA) << g;
            mskB |= (smax2(aB[g]) > thrB) << g;
        }

        // single fp32 pass: exp2((w - c)*K2 - mi*K2/32), flagged subgroups only
        float shA = (float)miA * SHIFTC;
        float shB = (float)miB * SHIFTC;
        float sA = 0.f, sB = 0.f;
#pragma unroll 1
        for (int q = 0; q < 4; q++) {
            int ix = (q << 6) + (lane << 1);
            if ((mskA >> (2 * q)) & 1) {
                float4 a = cfA[ix];     float4 w = ws4[ix];
                sA += exp2f(fmaf(w.x - a.x, K2F, -shA)) + exp2f(fmaf(w.y - a.y, K2F, -shA))
                    + exp2f(fmaf(w.z - a.z, K2F, -shA)) + exp2f(fmaf(w.w - a.w, K2F, -shA));
            }
            if ((mskA >> (2 * q + 1)) & 1) {
                float4 a = cfA[ix + 1]; float4 w = ws4[ix + 1];
                sA += exp2f(fmaf(w.x - a.x, K2F, -shA)) + exp2f(fmaf(w.y - a.y, K2F, -shA))
                    + exp2f(fmaf(w.z - a.z, K2F, -shA)) + exp2f(fmaf(w.w - a.w, K2F, -shA));
            }
            if ((mskB >> (2 * q)) & 1) {
                float4 a = cfB[ix];     float4 w = ws4[ix];
                sB += exp2f(fmaf(w.x - a.x, K2F, -shB)) + exp2f(fmaf(w.y - a.y, K2F, -shB))
                    + exp2f(fmaf(w.z - a.z, K2F, -shB)) + exp2f(fmaf(w.w - a.w, K2F, -shB));
            }
            if ((mskB >> (2 * q + 1)) & 1) {
                float4 a = cfB[ix + 1]; float4 w = ws4[ix + 1];
                sB += exp2f(fmaf(w.x - a.x, K2F, -shB)) + exp2f(fmaf(w.y - a.y, K2F, -shB))
                    + exp2f(fmaf(w.z - a.z, K2F, -shB)) + exp2f(fmaf(w.w - a.w, K2F, -shB));
            }
        }
        // interleaved sum reductions
#pragma unroll
        for (int o = 16; o; o >>= 1) {
            sA += __shfl_xor_sync(0xffffffffu, sA, o);
            sB += __shfl_xor_sync(0xffffffffu, sB, o);
        }

        if (lane == 0) {
            float zA = EPSLOGMU - (float)miA * QINV - EPSLN2F * log2f(sA);
            float zB = EPSLOGMU - (float)miB * QINV - EPSLN2F * log2f(sB);
            if (MODE0) {
                du_s[rlA]     = fabsf(zA - zdst[rowA]);
                du_s[rlA + 1] = fabsf(zB - zdst[rowA + 1]);
            }
            zdst[rowA]     = zA;
            zdst[rowA + 1] = zB;
        }
    }

    if (MODE0) {
        __syncthreads();
        if (wid == 0) {
            float e = du_s[lane] + du_s[lane + 32] + du_s[lane + 64] + du_s[lane + 96];
            e = wred_sum(e);
            if (lane == 0) g_bp[bid] = e;
        }
    }
}

// ---------------------------------------------------------------------------
// Persistent Sinkhorn kernel (champion control flow).
// ---------------------------------------------------------------------------
__global__ void __launch_bounds__(1024, 1) k_sink(float* __restrict__ out) {
    __shared__ float ws[1024];
    __shared__ float du_s[128];
    int tid  = threadIdx.x, bid = blockIdx.x;
    int lane = tid & 31,    wid = tid >> 5;

    // re-init per graph replay
    if (tid < 128) { int r = (bid << 7) + tid; g_u[r] = 0.f; g_v[r] = 0.f; }
    if (bid == 0 && tid == 0) g_done = 0;
    gbarrier();

    for (int it = 0; it < 100; it++) {
        int done = *(volatile int*)&g_done;     // frozen once latched (ref semantics)
        if (!done)
            scan_phase<true >(bid, tid, lane, wid, g_Cq,  g_C,  g_v, g_u, ws, du_s);
        gbarrier();
        if (!done) {
            if (bid == 0 && wid == 0) {         // err from this iteration's du
                float e = g_bp[lane] + g_bp[lane + 32] + g_bp[lane + 64] + g_bp[lane + 96];
                e = wred_sum(e);
                if (lane == 0 && e * (1.0f / 16.0f) < 0.1f) g_done = 1;
            }
            // triggering iteration's v-update still applied (matches reference)
            scan_phase<false>(bid, tid, lane, wid, g_CTq, g_CT, g_u, g_v, ws, du_s);
        }
        gbarrier();
    }

    // --------- final: sum_ij exp((u_i + v_j - C_ij)/eps) * C_ij ----------
    {
        int b = bid >> 3;
        ws[tid] = g_v[(b << 10) + tid];
        __syncthreads();
        const float4* ws4 = (const float4*)ws;
        unsigned wq[16];
        BUILD_WQ();

#pragma unroll 1
        for (int r = 0; r < 4; r++) {
            int rl  = (wid << 2) + r;
            int row = (bid << 7) + rl;
            const uint4*  cp  = (const uint4*) (g_Cq + ((size_t)row << 10));
            const float4* cf4 = (const float4*)(g_C  + ((size_t)row << 10));
            float uk = g_u[row];

            unsigned accs[8];
#pragma unroll
            for (int g = 0; g < 8; g++) accs[g] = 0x80008000u;
#pragma unroll
            for (int q = 0; q < 4; q++) {
                uint4 cq = cp[(q << 5) + lane];
                accs[2*q  ] = __viaddmax_s16x2(wq[q*4+0], cq.x, accs[2*q  ]);
                accs[2*q  ] = __viaddmax_s16x2(wq[q*4+1], cq.y, accs[2*q  ]);
                accs[2*q+1] = __viaddmax_s16x2(wq[q*4+2], cq.z, accs[2*q+1]);
                accs[2*q+1] = __viaddmax_s16x2(wq[q*4+3], cq.w, accs[2*q+1]);
            }

            // contribute iff (val + uk) > ~-0.03; generous slack for quantization
            int cutq = __float2int_rd((-0.6f - uk) * QSCALE);
            int msk = 0;
#pragma unroll
            for (int g = 0; g < 8; g++) msk |= (smax2(accs[g]) > cutq) << g;

            float s = 0.f;
#pragma unroll 1
            for (int q = 0; q < 4; q++) {
                int ix = (q << 6) + (lane << 1);
                if ((msk >> (2 * q)) & 1) {
                    float4 a  = cf4[ix];
                    float4 wa = ws4[ix];
                    s += exp2f((wa.x - a.x + uk) * K2F) * a.x
                       + exp2f((wa.y - a.y + uk) * K2F) * a.y
                       + exp2f((wa.z - a.z + uk) * K2F) * a.z
                       + exp2f((wa.w - a.w + uk) * K2F) * a.w;
                }
                if ((msk >> (2 * q + 1)) & 1) {
                    float4 bb = cf4[ix + 1];
                    float4 wb = ws4[ix + 1];
                    s += exp2f((wb.x - bb.x + uk) * K2F) * bb.x
                       + exp2f((wb.y - bb.y + uk) * K2F) * bb.y
                       + exp2f((wb.z - bb.z + uk) * K2F) * bb.z
                       + exp2f((wb.w - bb.w + uk) * K2F) * bb.w;
                }
            }
            s = wred_sum(s);
            if (lane == 0) du_s[rl] = s;
        }
        __syncthreads();
        if (wid == 0) {
            float e = du_s[lane] + du_s[lane + 32] + du_s[lane + 64] + du_s[lane + 96];
            e = wred_sum(e);
            if (lane == 0) g_bp[bid] = e;
        }
    }
    gbarrier();
    if (bid == 0 && wid == 0) {
        float e = g_bp[lane] + g_bp[lane + 32] + g_bp[lane + 64] + g_bp[lane + 96];
        e = wred_sum(e);
        if (lane == 0) out[0] = e * (1.0f / 16.0f);   // mean over B
    }
}

// ---------------------------------------------------------------------------
extern "C" void kernel_launch(void* const* d_in, const int* in_sizes, int n_in,
                              void* d_out, int out_size) {
    (void)in_sizes; (void)n_in; (void)out_size;
    const float* X = (const float*)d_in[0];   // output [16,1024,32]
    const float* Y = (const float*)d_in[1];   // labels [16,1024,32]

    k_cost<<<16384, 256>>>(X, Y);
    k_sink<<<NBLK, 1024>>>((float*)d_out);
}

// round 17
// speedup vs baseline: 1.4388x; 1.1682x over previous
#include <cuda_runtime.h>
#include <cstddef>

// Problem constants (B=16, N=M=1024, D=32)
#define CELEM (16 * 1024 * 1024)
#define ROWS  (16 * 1024)
#define NBLK  128                  // persistent blocks (co-resident, proven)

// eps = 1e-3
#define K2F       1442.6951f       // log2(e)/eps
#define EPSLN2F   6.9314718e-4f    // eps*ln2
#define EPSLOGMU  (-6.9314616e-3f) // eps*log(1/1024 + 1e-8)
#define QSCALE    32.0f            // s16 quantization scale
#define QINV      0.03125f         // 1/32
#define SHIFTC    45.084222f       // K2F / 32
#define MARGIN_U  5                // prefilter margin, s16 units (need > 2.89)

// Device scratch (allocation-free rule)
__device__ float g_C  [CELEM];     // fp32 C  (exp pass + final)
__device__ float g_CT [CELEM];     // fp32 C^T
__device__ short g_Cq [CELEM];     // s16  -round(32*C)   (DPX prefilter)
__device__ short g_CTq[CELEM];     // s16  -round(32*C^T)
__device__ float g_u[ROWS], g_v[ROWS];
__device__ float g_bp[NBLK];
__device__ int   g_bar_count;
__device__ volatile int g_bar_gen;
__device__ int   g_bbar_count[16 * 32];        // per-batch barrier, 128B-strided
__device__ volatile int g_bbar_gen[16 * 32];

// ---------------------------------------------------------------------------
// Global barrier: release fence before arrive; NO acquire flush after wait
// (cross-SM data is read via __ldcg -> L2-direct, stale L1 can't bite).
// ---------------------------------------------------------------------------
__device__ __forceinline__ void gbarrier() {
    __syncthreads();
    if (threadIdx.x == 0) {
        __threadfence();                       // release this block's stores
        int gen = g_bar_gen;
        if (atomicAdd(&g_bar_count, 1) == NBLK - 1) {
            g_bar_count = 0;
            __threadfence();
            g_bar_gen = gen + 1;
        } else {
            while (g_bar_gen == gen) __nanosleep(64);
        }
    }
    __syncthreads();
}

// Batch-local barrier: couples only the 8 blocks of one batch.
__device__ __forceinline__ void bbarrier(int b) {
    __syncthreads();
    if (threadIdx.x == 0) {
        __threadfence();                       // release
        int idx = b << 5;
        int gen = g_bbar_gen[idx];
        if (atomicAdd(&g_bbar_count[idx], 1) == 7) {
            g_bbar_count[idx] = 0;
            __threadfence();
            g_bbar_gen[idx] = gen + 1;
        } else {
            while (g_bbar_gen[idx] == gen) __nanosleep(32);
        }
    }
    __syncthreads();
}

__device__ __forceinline__ float wred_sum(float v) {
#pragma unroll
    for (int o = 16; o; o >>= 1) v += __shfl_xor_sync(0xffffffffu, v, o);
    return v;
}
__device__ __forceinline__ int smax2(unsigned p) {
    int lo = (int)(short)(p & 0xffffu);
    int hi = (int)(short)(p >> 16);
    return lo > hi ? lo : hi;
}
__device__ __forceinline__ unsigned packw(float a, float b) {
    int ia = __float2int_rn(a * QSCALE);
    int ib = __float2int_rn(b * QSCALE);
    return (unsigned)(ia & 0xffff) | ((unsigned)ib << 16);
}

#define BUILD_WQ() do {                                                         \
    _Pragma("unroll")                                                           \
    for (int q = 0; q < 4; q++) {                                               \
        float4 wa = ws4[(q << 6) + (lane << 1)];                                \
        float4 wb = ws4[(q << 6) + (lane << 1) + 1];                            \
        wq[q*4+0] = packw(wa.x, wa.y);                                          \
        wq[q*4+1] = packw(wa.z, wa.w);                                          \
        wq[q*4+2] = packw(wb.x, wb.y);                                          \
        wq[q*4+3] = packw(wb.z, wb.w);                                          \
    }                                                                           \
} while (0)

// ---------------------------------------------------------------------------
// Cost matrix (verified): fp32 C/C^T + quantized -32*C as s16.
// ---------------------------------------------------------------------------
__global__ void __launch_bounds__(256) k_cost(const float* __restrict__ X,
                                              const float* __restrict__ Y) {
    __shared__ float xs[32][33], ys[32][33], cs[32][33];
    int t  = blockIdx.x;
    int b  = t >> 10;
    int it = (t >> 5) & 31;
    int jt = t & 31;
    int tid = threadIdx.x;
    int r = tid >> 5, d = tid & 31;

#pragma unroll
    for (int k = 0; k < 4; k++) {
        int rr = r + (k << 3);
        xs[rr][d] = X[((size_t)b * 1024 + it * 32 + rr) * 32 + d];
        ys[rr][d] = Y[((size_t)b * 1024 + jt * 32 + rr) * 32 + d];
    }
    __syncthreads();

    int tx = tid & 31, ty = tid >> 5;
#pragma unroll
    for (int k = 0; k < 4; k++) {
        int i = ty * 4 + k;
        float acc = 0.f;
#pragma unroll
        for (int dd = 0; dd < 32; dd++) {
            float diff = xs[i][dd] - ys[tx][dd];
            acc = fmaf(diff, diff, acc);
        }
        cs[i][tx] = acc;
    }
    __syncthreads();

    size_t cbase = (size_t)b << 20;
#pragma unroll
    for (int k = 0; k < 4; k++) {
        int i = ty * 4 + k;
        size_t idx  = cbase + (size_t)(it * 32 + i) * 1024 + jt * 32 + tx;
        size_t idxT = cbase + (size_t)(jt * 32 + i) * 1024 + it * 32 + tx;
        float  cv  = cs[i][tx];
        float  cvT = cs[tx][i];
        g_C  [idx]  = cv;
        g_CT [idxT] = cvT;
        g_Cq [idx]  = (short)__float2int_rn(cv  * -QSCALE);
        g_CTq[idxT] = (short)__float2int_rn(cvT * -QSCALE);
    }
}

// ---------------------------------------------------------------------------
// One half-step for this block's 128 rows, in PAIRS per warp (R16 champion).
// Cross-block dual staged via __ldcg (L2-direct; barriers carry no acquire).
// ---------------------------------------------------------------------------
template <bool MODE0>
__device__ __forceinline__ void scan_phase(
    int bid, int tid, int lane, int wid,
    const short* __restrict__ Cq, const float* __restrict__ Cf,
    const float* __restrict__ wsrc, float* __restrict__ zdst,
    float* ws, float* du_s)
{
    int b = bid >> 3;                       // batch of this block's 128 rows
    ws[tid] = __ldcg(wsrc + (b << 10) + tid);   // cross-SM read: L2-direct
    __syncthreads();

    const float4* ws4 = (const float4*)ws;
    unsigned wq[16];
    BUILD_WQ();

#pragma unroll 1
    for (int p = 0; p < 2; p++) {
        int rlA  = (wid << 2) + (p << 1);
        int rowA = (bid << 7) + rlA;
        const uint4*  cpA = (const uint4*) (Cq + ((size_t)rowA << 10));
        const uint4*  cpB = (const uint4*) (Cq + ((size_t)(rowA + 1) << 10));
        const float4* cfA = (const float4*)(Cf + ((size_t)rowA << 10));
        const float4* cfB = (const float4*)(Cf + ((size_t)(rowA + 1) << 10));

        unsigned aA[8], aB[8];
#pragma unroll
        for (int g = 0; g < 8; g++) { aA[g] = 0x80008000u; aB[g] = 0x80008000u; }

        // interleaved loads + DPX chains (2x MLP, 2 independent dep chains)
#pragma unroll
        for (int q = 0; q < 4; q++) {
            uint4 cA = cpA[(q << 5) + lane];
            uint4 cB = cpB[(q << 5) + lane];
            aA[2*q  ] = __viaddmax_s16x2(wq[q*4+0], cA.x, aA[2*q  ]);
            aB[2*q  ] = __viaddmax_s16x2(wq[q*4+0], cB.x, aB[2*q  ]);
            aA[2*q  ] = __viaddmax_s16x2(wq[q*4+1], cA.y, aA[2*q  ]);
            aB[2*q  ] = __viaddmax_s16x2(wq[q*4+1], cB.y, aB[2*q  ]);
            aA[2*q+1] = __viaddmax_s16x2(wq[q*4+2], cA.z, aA[2*q+1]);
            aB[2*q+1] = __viaddmax_s16x2(wq[q*4+2], cB.z, aB[2*q+1]);
            aA[2*q+1] = __viaddmax_s16x2(wq[q*4+3], cA.w, aA[2*q+1]);
            aB[2*q+1] = __viaddmax_s16x2(wq[q*4+3], cB.w, aB[2*q+1]);
        }

        // packed row max + interleaved warp reductions
        unsigned mmA = __vmaxs2(__vmaxs2(__vmaxs2(aA[0], aA[1]), __vmaxs2(aA[2], aA[3])),
                                __vmaxs2(__vmaxs2(aA[4], aA[5]), __vmaxs2(aA[6], aA[7])));
        unsigned mmB = __vmaxs2(__vmaxs2(__vmaxs2(aB[0], aB[1]), __vmaxs2(aB[2], aB[3])),
                                __vmaxs2(__vmaxs2(aB[4], aB[5]), __vmaxs2(aB[6], aB[7])));
#pragma unroll
        for (int o = 16; o; o >>= 1) {
            mmA = __vmaxs2(mmA, __shfl_xor_sync(0xffffffffu, mmA, o));
            mmB = __vmaxs2(mmB, __shfl_xor_sync(0xffffffffu, mmB, o));
        }
        int miA = smax2(mmA), miB = smax2(mmB);

        int thrA = miA - MARGIN_U, thrB = miB - MARGIN_U;
        int mskA = 0, mskB = 0;
#pragma unroll
        for (int g = 0; g < 8; g++) {
            mskA |= (smax2(aA[g]) > thrA) << g;
            mskB |= (smax2(aB[g]) > thrB) << g;
        }

        // single fp32 pass: exp2((w - c)*K2 - mi*K2/32), flagged subgroups only
        float shA = (float)miA * SHIFTC;
        float shB = (float)miB * SHIFTC;
        float sA = 0.f, sB = 0.f;
#pragma unroll 1
        for (int q = 0; q < 4; q++) {
            int ix = (q << 6) + (lane << 1);
            if ((mskA >> (2 * q)) & 1) {
                float4 a = cfA[ix];     float4 w = ws4[ix];
                sA += exp2f(fmaf(w.x - a.x, K2F, -shA)) + exp2f(fmaf(w.y - a.y, K2F, -shA))
                    + exp2f(fmaf(w.z - a.z, K2F, -shA)) + exp2f(fmaf(w.w - a.w, K2F, -shA));
            }
            if ((mskA >> (2 * q + 1)) & 1) {
                float4 a = cfA[ix + 1]; float4 w = ws4[ix + 1];
                sA += exp2f(fmaf(w.x - a.x, K2F, -shA)) + exp2f(fmaf(w.y - a.y, K2F, -shA))
                    + exp2f(fmaf(w.z - a.z, K2F, -shA)) + exp2f(fmaf(w.w - a.w, K2F, -shA));
            }
            if ((mskB >> (2 * q)) & 1) {
                float4 a = cfB[ix];     float4 w = ws4[ix];
                sB += exp2f(fmaf(w.x - a.x, K2F, -shB)) + exp2f(fmaf(w.y - a.y, K2F, -shB))
                    + exp2f(fmaf(w.z - a.z, K2F, -shB)) + exp2f(fmaf(w.w - a.w, K2F, -shB));
            }
            if ((mskB >> (2 * q + 1)) & 1) {
                float4 a = cfB[ix + 1]; float4 w = ws4[ix + 1];
                sB += exp2f(fmaf(w.x - a.x, K2F, -shB)) + exp2f(fmaf(w.y - a.y, K2F, -shB))
                    + exp2f(fmaf(w.z - a.z, K2F, -shB)) + exp2f(fmaf(w.w - a.w, K2F, -shB));
            }
        }
#pragma unroll
        for (int o = 16; o; o >>= 1) {
            sA += __shfl_xor_sync(0xffffffffu, sA, o);
            sB += __shfl_xor_sync(0xffffffffu, sB, o);
        }

        if (lane == 0) {
            float zA = EPSLOGMU - (float)miA * QINV - EPSLN2F * log2f(sA);
            float zB = EPSLOGMU - (float)miB * QINV - EPSLN2F * log2f(sB);
            if (MODE0) {
                du_s[rlA]     = fabsf(zA - zdst[rowA]);        // own-SM data
                du_s[rlA + 1] = fabsf(zB - zdst[rowA + 1]);
            }
            zdst[rowA]     = zA;
            zdst[rowA + 1] = zB;
        }
    }

    if (MODE0) {
        __syncthreads();
        if (wid == 0) {
            float e = du_s[lane] + du_s[lane + 32] + du_s[lane + 64] + du_s[lane + 96];
            e = wred_sum(e);
            if (lane == 0) g_bp[bid] = e;
        }
    }
}

// ---------------------------------------------------------------------------
// Persistent Sinkhorn kernel: batch-local barrier mid-iteration, one global
// barrier + all-blocks-identical err latch (uniform break) per iteration.
// ---------------------------------------------------------------------------
__global__ void __launch_bounds__(1024, 1) k_sink(float* __restrict__ out) {
    __shared__ float ws[1024];
    __shared__ float du_s[128];
    __shared__ float s_red[1];
    int tid  = threadIdx.x, bid = blockIdx.x;
    int lane = tid & 31,    wid = tid >> 5;
    int batch = bid >> 3;

    // re-init per graph replay
    if (tid < 128) { int r = (bid << 7) + tid; g_u[r] = 0.f; g_v[r] = 0.f; }
    gbarrier();

    for (int it = 0; it < 100; it++) {
        // ---- u-update (reads v of this batch) ----
        scan_phase<true >(bid, tid, lane, wid, g_Cq,  g_C,  g_v, g_u, ws, du_s);
        bbarrier(batch);                       // only this batch's 8 blocks couple

        // ---- v-update (reads u of this batch; triggering v still applied) ----
        scan_phase<false>(bid, tid, lane, wid, g_CTq, g_CT, g_u, g_v, ws, du_s);
        gbarrier();

        // err latch: identical deterministic reduction in EVERY block
        if (tid < 32) {
            float a = __ldcg(&g_bp[lane])      + __ldcg(&g_bp[lane + 32])
                    + __ldcg(&g_bp[lane + 64]) + __ldcg(&g_bp[lane + 96]);
            a = wred_sum(a);
            if (lane == 0) s_red[0] = a;
        }
        __syncthreads();
        if (s_red[0] * (1.0f / 16.0f) < 0.1f) break;   // uniform across blocks
    }

    // --------- final: sum_ij exp((u_i + v_j - C_ij)/eps) * C_ij ----------
    {
        ws[tid] = __ldcg(g_v + (batch << 10) + tid);
        __syncthreads();
        const float4* ws4 = (const float4*)ws;
        unsigned wq[16];
        BUILD_WQ();

#pragma unroll 1
        for (int r = 0; r < 4; r++) {
            int rl  = (wid << 2) + r;
            int row = (bid << 7) + rl;
            const uint4*  cp  = (const uint4*) (g_Cq + ((size_t)row << 10));
            const float4* cf4 = (const float4*)(g_C  + ((size_t)row << 10));
            float uk = g_u[row];               // own-SM data

            unsigned accs[8];
#pragma unroll
            for (int g = 0; g < 8; g++) accs[g] = 0x80008000u;
#pragma unroll
            for (int q = 0; q < 4; q++) {
                uint4 cq = cp[(q << 5) + lane];
                accs[2*q  ] = __viaddmax_s16x2(wq[q*4+0], cq.x, accs[2*q  ]);
                accs[2*q  ] = __viaddmax_s16x2(wq[q*4+1], cq.y, accs[2*q  ]);
                accs[2*q+1] = __viaddmax_s16x2(wq[q*4+2], cq.z, accs[2*q+1]);
                accs[2*q+1] = __viaddmax_s16x2(wq[q*4+3], cq.w, accs[2*q+1]);
            }

            int cutq = __float2int_rd((-0.6f - uk) * QSCALE);
            int msk = 0;
#pragma unroll
            for (int g = 0; g < 8; g++) msk |= (smax2(accs[g]) > cutq) << g;

            float s = 0.f;
#pragma unroll 1
            for (int q = 0; q < 4; q++) {
                int ix = (q << 6) + (lane << 1);
                if ((msk >> (2 * q)) & 1) {
                    float4 a  = cf4[ix];
                    float4 wa = ws4[ix];
                    s += exp2f((wa.x - a.x + uk) * K2F) * a.x
                       + exp2f((wa.y - a.y + uk) * K2F) * a.y
                       + exp2f((wa.z - a.z + uk) * K2F) * a.z
                       + exp2f((wa.w - a.w + uk) * K2F) * a.w;
                }
                if ((msk >> (2 * q + 1)) & 1) {
                    float4 bb = cf4[ix + 1];
                    float4 wb = ws4[ix + 1];
                    s += exp2f((wb.x - bb.x + uk) * K2F) * bb.x
                       + exp2f((wb.y - bb.y + uk) * K2F) * bb.y
                       + exp2f((wb.z - bb.z + uk) * K2F) * bb.z
                       + exp2f((wb.w - bb.w + uk) * K2F) * bb.w;
                }
            }
            s = wred_sum(s);
            if (lane == 0) du_s[rl] = s;
        }
        __syncthreads();
        if (wid == 0) {
            float e = du_s[lane] + du_s[lane + 32] + du_s[lane + 64] + du_s[lane + 96];
            e = wred_sum(e);
            if (lane == 0) g_bp[bid] = e;
        }
    }
    gbarrier();
    if (bid == 0 && wid == 0) {
        float e = __ldcg(&g_bp[lane])      + __ldcg(&g_bp[lane + 32])
                + __ldcg(&g_bp[lane + 64]) + __ldcg(&g_bp[lane + 96]);
        e = wred_sum(e);
        if (lane == 0) out[0] = e * (1.0f / 16.0f);   // mean over B
    }
}

// ---------------------------------------------------------------------------
extern "C" void kernel_launch(void* const* d_in, const int* in_sizes, int n_in,
                              void* d_out, int out_size) {
    (void)in_sizes; (void)n_in; (void)out_size;
    const float* X = (const float*)d_in[0];   // output [16,1024,32]
    const float* Y = (const float*)d_in[1];   // labels [16,1024,32]

    k_cost<<<16384, 256>>>(X, Y);
    k_sink<<<NBLK, 1024>>>((float*)d_out);
}